// round 14
// baseline (speedup 1.0000x reference)
#include <cuda_runtime.h>
#include <cuda_bf16.h>
#include <cuda_fp16.h>
#include <math.h>
#include <stdint.h>

// Problem constants (fixed by setup_inputs)
#define BATCH 4
#define SEQ   2048
#define DMODEL 1024
#define NHEAD 16
#define DHEAD 64
#define BHD   (BATCH * NHEAD)          // 64
#define MTOT  (BATCH * SEQ)            // 8192
#define NQKV  (3 * DMODEL)             // 3072

// ---------------------------------------------------------------------------
// Scratch (sanctioned: __device__ globals)
// GEMM operands fp16 hi-only: [k-chunk(32)][row][64B], 16B segs swizzled
// by (seg ^ ((row>>1)&3)). One (chunk,128-row) slice = contiguous 8 KB.
// ---------------------------------------------------------------------------
__device__ __align__(128) char g_xpk [(size_t)MTOT  * DMODEL * 2];
__device__ __align__(128) char g_wqpk[(size_t)NQKV  * DMODEL * 2];
__device__ __align__(128) char g_wfpk[(size_t)DMODEL* DMODEL * 2];
__device__ __align__(128) char g_opk [(size_t)MTOT  * DMODEL * 2];
// q/k/v for attention: fp16, [b,h,s,dh] (written by qkv GEMM epilogue)
__device__ __align__(128) __half g_q[BHD * SEQ * DHEAD];
__device__ __align__(128) __half g_k[BHD * SEQ * DHEAD];
__device__ __align__(128) __half g_v[BHD * SEQ * DHEAD];

// ---------------------------------------------------------------------------
// helpers
// ---------------------------------------------------------------------------
__device__ __forceinline__ uint32_t smem_u32(const void* p) {
    uint32_t a;
    asm("{ .reg .u64 t; cvta.to.shared.u64 t, %1; cvt.u32.u64 %0, t; }"
        : "=r"(a) : "l"(p));
    return a;
}

#define LDSM_X4(r0, r1, r2, r3, addr)                                       \
    asm volatile("ldmatrix.sync.aligned.m8n8.x4.shared.b16 {%0,%1,%2,%3}, [%4];" \
                 : "=r"(r0), "=r"(r1), "=r"(r2), "=r"(r3) : "r"(addr))

#define LDSM_X4_T(r0, r1, r2, r3, addr)                                     \
    asm volatile("ldmatrix.sync.aligned.m8n8.x4.trans.shared.b16 {%0,%1,%2,%3}, [%4];" \
                 : "=r"(r0), "=r"(r1), "=r"(r2), "=r"(r3) : "r"(addr))

__device__ __forceinline__ void mma_fp16(float* d, const uint32_t* a,
                                         uint32_t b0, uint32_t b1) {
    asm volatile(
        "mma.sync.aligned.m16n8k16.row.col.f32.f16.f16.f32 "
        "{%0,%1,%2,%3}, {%4,%5,%6,%7}, {%8,%9}, {%0,%1,%2,%3};"
        : "+f"(d[0]), "+f"(d[1]), "+f"(d[2]), "+f"(d[3])
        : "r"(a[0]), "r"(a[1]), "r"(a[2]), "r"(a[3]), "r"(b0), "r"(b1));
}

#define CP_ASYNC16(dst, src) \
    asm volatile("cp.async.cg.shared.global [%0], [%1], 16;" \
                 :: "r"(dst), "l"(src) : "memory")
#define CP_COMMIT()  asm volatile("cp.async.commit_group;" ::: "memory")
#define CP_WAIT(n)   asm volatile("cp.async.wait_group %0;" :: "n"(n) : "memory")

#define MBAR_INIT(addr, cnt) \
    asm volatile("mbarrier.init.shared.b64 [%0], %1;" :: "r"(addr), "r"((uint32_t)(cnt)) : "memory")
#define MBAR_EXPECT_TX(addr, bytes) \
    asm volatile("mbarrier.arrive.expect_tx.shared.b64 _, [%0], %1;" \
                 :: "r"(addr), "r"((uint32_t)(bytes)) : "memory")
#define MBAR_ARRIVE(addr) \
    asm volatile("mbarrier.arrive.shared.b64 _, [%0];" :: "r"(addr) : "memory")
#define BULK_G2S(dst, src, bytes, mbar) \
    asm volatile("cp.async.bulk.shared::cluster.global.mbarrier::complete_tx::bytes " \
                 "[%0], [%1], %2, [%3];" \
                 :: "r"(dst), "l"(src), "r"((uint32_t)(bytes)), "r"(mbar) : "memory")

__device__ __forceinline__ void mbar_wait(uint32_t addr, uint32_t parity) {
    asm volatile(
        "{\n\t.reg .pred P;\n\t"
        "WL%=:\n\t"
        "mbarrier.try_wait.parity.acquire.cta.shared::cta.b64 P, [%0], %1, 0x989680;\n\t"
        "@!P bra WL%=;\n\t}"
        :: "r"(addr), "r"(parity) : "memory");
}

__device__ __forceinline__ uint32_t pack2h(float a, float b) {
    __half2 h = __floats2half2_rn(a, b);
    return *(uint32_t*)&h;
}

// exp2 via magic-number rounding + deg-5 poly + exponent-bit add (no MUFU).
__device__ __forceinline__ float exp2_poly(float x) {
    x = fmaxf(x, -80.0f);
    float t = x + 12582912.0f;
    float fn = t - 12582912.0f;
    float f = x - fn;
    float p = 1.3333558e-3f;
    p = fmaf(p, f, 9.6181291e-3f);
    p = fmaf(p, f, 5.5504109e-2f);
    p = fmaf(p, f, 2.4022651e-1f);
    p = fmaf(p, f, 6.9314718e-1f);
    p = fmaf(p, f, 1.0f);
    int n = (__float_as_int(t) & 0x7FFFFF) - 0x400000;
    return __int_as_float(__float_as_int(p) + (n << 23));
}

// ---------------------------------------------------------------------------
// Pre-pass: fp32 [M,1024] -> packed swizzled fp16 hi-only chunks (64B rows)
// ---------------------------------------------------------------------------
__global__ __launch_bounds__(256) void split_pack_b_kernel(
    const float* __restrict__ src, char* __restrict__ dst, int M)
{
    const int total = M * 128;
    for (int idx = blockIdx.x * blockDim.x + threadIdx.x; idx < total;
         idx += gridDim.x * blockDim.x) {
        const int m   = idx >> 7;
        const int k   = (idx & 127) << 3;
        const int c   = k >> 5;
        const int seg = (k & 31) >> 3;   // 0..3
        const float4 v0 = *(const float4*)(src + (size_t)m * DMODEL + k);
        const float4 v1 = *(const float4*)(src + (size_t)m * DMODEL + k + 4);
        char* row = dst + ((size_t)c * M + m) * 64;
        const int sx = (m >> 1) & 3;
        *(uint4*)(row + ((seg ^ sx) << 4)) =
            make_uint4(pack2h(v0.x, v0.y), pack2h(v0.z, v0.w),
                       pack2h(v1.x, v1.y), pack2h(v1.z, v1.w));
    }
}

// ---------------------------------------------------------------------------
// fp16 1-pass GEMM: C = Ah * Bh^T.
// 128x128 CTA tile, 4 warps (2x2 grid of 64x64 warp tiles), 128 threads,
// 3 CTA/SM. K-chunk 64 (two packed 32-sub-chunks). Stage = 32KB, 2 stages.
// cp.async.bulk + full/empty mbarrier ring (no __syncthreads in mainloop).
// mode 0: C = x @ w_qkv^T, scatter fp16 into g_q/g_k/g_v [b,h,s,dh]
// mode 1: C = O @ w_fc^T + b_fc, write fp32 out
// ---------------------------------------------------------------------------
#define NCHK   16
#define STG_B  32768
#define DSMEM_BYTES (2 * STG_B)   // 65536

__global__ __launch_bounds__(128, 3) void gemm_pk_kernel(
    const char* __restrict__ Apk, const char* __restrict__ Bpk,
    int Mtot, int Ntot,
    const float* __restrict__ bias, float* __restrict__ out, int mode)
{
    extern __shared__ __align__(128) char dsm[];
    __shared__ __align__(8) uint64_t fullb[2];
    __shared__ __align__(8) uint64_t emptyb[2];
    const uint32_t sbase = smem_u32(dsm);
    const uint32_t fb0 = smem_u32(&fullb[0]);
    const uint32_t eb0 = smem_u32(&emptyb[0]);

    const int tid  = threadIdx.x;
    const int lane = tid & 31;
    const int warp = tid >> 5;             // 0..3
    const int bm = blockIdx.y * 128;
    const int bn = blockIdx.x * 128;
    const int warp_m = (warp >> 1) << 6;   // 0 or 64
    const int warp_n = (warp & 1) << 6;    // 0 or 64

    if (tid == 0) {
#pragma unroll
        for (int s = 0; s < 2; ++s) {
            MBAR_INIT(fb0 + s * 8, 1);
            MBAR_INIT(eb0 + s * 8, 4);
        }
    }
    __syncthreads();

    auto issue = [&](int c) {
        const int st = c & 1;
        const uint32_t mb = fb0 + st * 8;
        const uint32_t sb = sbase + st * STG_B;
        MBAR_EXPECT_TX(mb, 32768);
        BULK_G2S(sb,         Apk + ((size_t)(2*c)   * Mtot + bm) * 64, 8192, mb);
        BULK_G2S(sb + 8192,  Apk + ((size_t)(2*c+1) * Mtot + bm) * 64, 8192, mb);
        BULK_G2S(sb + 16384, Bpk + ((size_t)(2*c)   * Ntot + bn) * 64, 8192, mb);
        BULK_G2S(sb + 24576, Bpk + ((size_t)(2*c+1) * Ntot + bn) * 64, 8192, mb);
    };

    if (tid == 0) { issue(0); issue(1); }

    float acc[4][8][4];
#pragma unroll
    for (int i = 0; i < 4; i++)
#pragma unroll
        for (int j = 0; j < 8; j++)
#pragma unroll
            for (int r = 0; r < 4; r++) acc[i][j][r] = 0.f;

    const int r16 = lane & 15;
    const int cs  = lane >> 4;          // 0/1
    const int sx  = (r16 >> 1) & 3;     // 64B-row swizzle

    for (int c = 0; c < NCHK; ++c) {
        const int st = c & 1;
        mbar_wait(fb0 + st * 8, (c >> 1) & 1);   // per-warp gate

#pragma unroll
        for (int kb = 0; kb < 2; ++kb) {
            const uint32_t Ast = sbase + st * STG_B + kb * 8192;
            const uint32_t Bst = Ast + 16384;
#pragma unroll
            for (int kh = 0; kh < 2; ++kh) {
                const int seg = kh * 2 + cs;        // 0..3
                uint32_t ah[4][4];
#pragma unroll
                for (int mi = 0; mi < 4; ++mi) {
                    const uint32_t ad = Ast + (warp_m + (mi << 4) + r16) * 64
                                        + ((seg ^ sx) << 4);
                    LDSM_X4(ah[mi][0], ah[mi][1], ah[mi][2], ah[mi][3], ad);
                }
#pragma unroll
                for (int g = 0; g < 4; ++g) {
                    const uint32_t bd = Bst + (warp_n + (g << 4) + r16) * 64
                                        + ((seg ^ sx) << 4);
                    uint32_t t0, t1, t2, t3;
                    LDSM_X4(t0, t1, t2, t3, bd);
#pragma unroll
                    for (int mi = 0; mi < 4; ++mi) {
                        mma_fp16(acc[mi][g * 2],     ah[mi], t0, t2);
                        mma_fp16(acc[mi][g * 2 + 1], ah[mi], t1, t3);
                    }
                }
            }
        }

        if (lane == 0) MBAR_ARRIVE(eb0 + st * 8);   // this warp done with st

        // producer: stage st is reused by chunk c+2; wait this chunk's 4
        // consumer arrivals, then issue.
        if (tid == 0 && c + 2 < NCHK) {
            mbar_wait(eb0 + st * 8, (c >> 1) & 1);
            issue(c + 2);
        }
    }

    // ---- epilogue ----
    const int er = lane >> 2;          // 0..7
    const int ec = (lane & 3) << 1;    // 0,2,4,6
#pragma unroll
    for (int mi = 0; mi < 4; ++mi) {
#pragma unroll
        for (int nj = 0; nj < 8; ++nj) {
            const int m = bm + warp_m + (mi << 4) + er;
            const int n = bn + warp_n + (nj << 3) + ec;
            if (mode == 0) {
                const int bb = m >> 11;
                const int ss = m & (SEQ - 1);
                const int sec = n >> 10;
                const int e = n & (DMODEL - 1);
                const int h = e >> 6;
                const int dh = e & 63;
                __half* dst = (sec == 0 ? g_q : (sec == 1 ? g_k : g_v));
                const long idx = ((long)(bb * NHEAD + h) * SEQ + ss) * DHEAD + dh;
                *(uint32_t*)(dst + idx) = pack2h(acc[mi][nj][0], acc[mi][nj][1]);
                *(uint32_t*)(dst + idx + 8 * DHEAD) =
                    pack2h(acc[mi][nj][2], acc[mi][nj][3]);
            } else {
                const float2 bv = *(const float2*)(bias + n);
                float* dst = out + (long)m * DMODEL + n;
                *(float2*)dst = make_float2(acc[mi][nj][0] + bv.x, acc[mi][nj][1] + bv.y);
                *(float2*)(dst + 8 * DMODEL) =
                    make_float2(acc[mi][nj][2] + bv.x, acc[mi][nj][3] + bv.y);
            }
        }
    }
}

// ---------------------------------------------------------------------------
// Attention via fp16 1-pass mma.sync: 128 queries/CTA, 8 warps (16 q-rows
// each), key tiles of 64. Epilogue writes packed-swizzled fp16 O.
// ---------------------------------------------------------------------------
#define APITCH 144
#define QTILE  (128 * APITCH)              // 18432
#define KVTILE (64 * APITCH)               // 9216
#define ASMEM  (QTILE + 2 * KVTILE + 256)

__global__ __launch_bounds__(256) void attn_mma_kernel(
    const int* __restrict__ mask, const int* __restrict__ use_g_p,
    const float* __restrict__ shift_p, const float* __restrict__ bias_pp)
{
    extern __shared__ __align__(128) char asmem[];
    const uint32_t QT = smem_u32(asmem);
    const uint32_t KT = QT + QTILE;
    const uint32_t VT = KT + KVTILE;
    float* msk_s = (float*)(asmem + QTILE + 2 * KVTILE);

    const int bh = blockIdx.y;
    const int bb = bh >> 4;
    const int q0 = blockIdx.x * 128;
    const int tid  = threadIdx.x;
    const int lane = tid & 31;
    const int warp = tid >> 5;             // 0..7

    const float LOG2E = 1.4426950408889634f;
    const float shift = shift_p[0];
    const int   useg  = use_g_p[0];
    const float sg = useg ? shift * LOG2E : 0.f;
    const float bg = useg ? bias_pp[0] * LOG2E : 0.f;
    const float SCL = 0.125f * LOG2E;

    int klo = 0, khi = SEQ;
    if (useg) {
        const int Wi = (int)sqrtf(44.f / shift) + 50;
        klo = q0 - Wi;             if (klo < 0)   klo = 0;   klo &= ~63;
        khi = (q0 + 128 + Wi + 63) & ~63;
        if (khi > SEQ) khi = SEQ;
    }

    // Q tile: 128 rows x 64 halves; 1024 x 16B transfers over 256 threads
    const long qgb = (long)(bh * SEQ + q0) * DHEAD;
#pragma unroll
    for (int it = 0; it < 4; ++it) {
        const int i = tid + (it << 8);
        const int r = i >> 3, ch = (i & 7) << 4;
        CP_ASYNC16(QT + r * APITCH + ch, (const char*)(g_q + qgb + r * DHEAD) + ch);
    }
    CP_COMMIT();
    CP_WAIT(0);
    __syncthreads();

    uint32_t aq[4][4];
    {
        const uint32_t ad0 = QT + (warp * 16 + (lane & 15)) * APITCH
                             + ((lane >> 4) << 4);
#pragma unroll
        for (int kk = 0; kk < 4; kk++)
            LDSM_X4(aq[kk][0], aq[kk][1], aq[kk][2], aq[kk][3], ad0 + kk * 32);
    }

    float o[8][4];
#pragma unroll
    for (int nb = 0; nb < 8; nb++)
#pragma unroll
        for (int r = 0; r < 4; r++) o[nb][r] = 0.f;
    float m_i[2] = {-3.0e5f, -3.0e5f};
    float l_i[2] = {0.f, 0.f};

    const int qi0 = q0 + warp * 16 + (lane >> 2);
    const int cj0 = (lane & 3) << 1;

    for (int kt = klo; kt < khi; kt += 64) {
        __syncthreads();
        // K/V tiles: 64 rows x 64 halves each = 512 transfers each
        {
            const int i = tid;
            const int r = i >> 3, ch = (i & 7) << 4;
            const long gb = (long)(bh * SEQ + kt + r) * DHEAD;
            CP_ASYNC16(KT + r * APITCH + ch, (const char*)(g_k + gb) + ch);
            CP_ASYNC16(VT + r * APITCH + ch, (const char*)(g_v + gb) + ch);
            const int i2 = tid + 256;
            const int r2 = i2 >> 3, ch2 = (i2 & 7) << 4;
            const long gb2 = (long)(bh * SEQ + kt + r2) * DHEAD;
            CP_ASYNC16(KT + r2 * APITCH + ch2, (const char*)(g_k + gb2) + ch2);
            CP_ASYNC16(VT + r2 * APITCH + ch2, (const char*)(g_v + gb2) + ch2);
        }
        if (tid < 64) msk_s[tid] = (mask[bb * SEQ + kt + tid] != 0) ? 0.f : -1.0e5f;
        CP_COMMIT();
        CP_WAIT(0);
        __syncthreads();

        float s[8][4];
#pragma unroll
        for (int nb = 0; nb < 8; nb++)
#pragma unroll
            for (int r = 0; r < 4; r++) s[nb][r] = 0.f;

#pragma unroll
        for (int kk = 0; kk < 4; kk++) {
#pragma unroll
            for (int g = 0; g < 4; g++) {
                const uint32_t bd = KT + (g * 16 + (lane & 15)) * APITCH
                                    + kk * 32 + ((lane >> 4) << 4);
                uint32_t t0, t1, t2, t3;
                LDSM_X4(t0, t1, t2, t3, bd);
                mma_fp16(s[g * 2],     aq[kk], t0, t2);
                mma_fp16(s[g * 2 + 1], aq[kk], t1, t3);
            }
        }

        float mx0 = -3.0e38f, mx1 = -3.0e38f;
#pragma unroll
        for (int nb = 0; nb < 8; nb++) {
            const int kj = kt + nb * 8 + cj0;
            const float mk0 = msk_s[nb * 8 + cj0];
            const float mk1 = msk_s[nb * 8 + cj0 + 1];
            const float d00 = (float)(qi0 - kj);
            const float d01 = d00 - 1.f;
            const float d20 = d00 + 8.f;
            const float d21 = d01 + 8.f;
            s[nb][0] = fmaf(s[nb][0], SCL, mk0) - fmaf(sg * d00, d00, bg);
            s[nb][1] = fmaf(s[nb][1], SCL, mk1) - fmaf(sg * d01, d01, bg);
            s[nb][2] = fmaf(s[nb][2], SCL, mk0) - fmaf(sg * d20, d20, bg);
            s[nb][3] = fmaf(s[nb][3], SCL, mk1) - fmaf(sg * d21, d21, bg);
            mx0 = fmaxf(mx0, fmaxf(s[nb][0], s[nb][1]));
            mx1 = fmaxf(mx1, fmaxf(s[nb][2], s[nb][3]));
        }
        mx0 = fmaxf(mx0, __shfl_xor_sync(0xffffffffu, mx0, 1));
        mx0 = fmaxf(mx0, __shfl_xor_sync(0xffffffffu, mx0, 2));
        mx1 = fmaxf(mx1, __shfl_xor_sync(0xffffffffu, mx1, 1));
        mx1 = fmaxf(mx1, __shfl_xor_sync(0xffffffffu, mx1, 2));
        const float mn0 = fmaxf(m_i[0], mx0);
        const float mn1 = fmaxf(m_i[1], mx1);
        const float cr0 = exp2_poly(m_i[0] - mn0);
        const float cr1 = exp2_poly(m_i[1] - mn1);
        m_i[0] = mn0; m_i[1] = mn1;

        float rs0 = 0.f, rs1 = 0.f;
#pragma unroll
        for (int nb = 0; nb < 8; nb++) {
            s[nb][0] = exp2_poly(s[nb][0] - mn0);
            s[nb][1] = exp2_poly(s[nb][1] - mn0);
            s[nb][2] = exp2_poly(s[nb][2] - mn1);
            s[nb][3] = exp2_poly(s[nb][3] - mn1);
            rs0 += s[nb][0] + s[nb][1];
            rs1 += s[nb][2] + s[nb][3];
        }
        rs0 += __shfl_xor_sync(0xffffffffu, rs0, 1);
        rs0 += __shfl_xor_sync(0xffffffffu, rs0, 2);
        rs1 += __shfl_xor_sync(0xffffffffu, rs1, 1);
        rs1 += __shfl_xor_sync(0xffffffffu, rs1, 2);
        l_i[0] = l_i[0] * cr0 + rs0;
        l_i[1] = l_i[1] * cr1 + rs1;
#pragma unroll
        for (int nb = 0; nb < 8; nb++) {
            o[nb][0] *= cr0; o[nb][1] *= cr0;
            o[nb][2] *= cr1; o[nb][3] *= cr1;
        }

#pragma unroll
        for (int kk = 0; kk < 4; kk++) {
            uint32_t ph[4];
            ph[0] = pack2h(s[2 * kk][0],     s[2 * kk][1]);
            ph[1] = pack2h(s[2 * kk][2],     s[2 * kk][3]);
            ph[2] = pack2h(s[2 * kk + 1][0], s[2 * kk + 1][1]);
            ph[3] = pack2h(s[2 * kk + 1][2], s[2 * kk + 1][3]);
#pragma unroll
            for (int gn = 0; gn < 4; gn++) {
                const uint32_t vd = VT + (kk * 16 + (lane & 15)) * APITCH
                                    + gn * 32 + ((lane >> 4) << 4);
                uint32_t t0, t1, t2, t3;
                LDSM_X4_T(t0, t1, t2, t3, vd);
                mma_fp16(o[gn * 2],     ph, t0, t1);
                mma_fp16(o[gn * 2 + 1], ph, t2, t3);
            }
        }
    }

    // ---- normalize + write O in packed-swizzled fp16 hi-only layout ----
    const float inv0 = 1.f / l_i[0];
    const float inv1 = 1.f / l_i[1];
    const int h = bh & 15;
    const int mrow = bb * SEQ + q0 + warp * 16 + (lane >> 2);
    const int swx = (mrow >> 1) & 3;   // (mrow+8) gives same swx (mod 4)
#pragma unroll
    for (int nb = 0; nb < 8; nb++) {
        const int d0 = nb * 8 + cj0;
        const int c  = 2 * h + (d0 >> 5);
        const int kk = d0 & 31;
        const int off = (((kk >> 3) ^ swx) << 4) + ((kk & 7) << 1);
        char* r1 = g_opk + ((size_t)c * MTOT + mrow) * 64;
        char* r2 = r1 + 8 * 64;
        *(uint32_t*)(r1 + off) = pack2h(o[nb][0] * inv0, o[nb][1] * inv0);
        *(uint32_t*)(r2 + off) = pack2h(o[nb][2] * inv1, o[nb][3] * inv1);
    }
}

// ---------------------------------------------------------------------------
extern "C" void kernel_launch(void* const* d_in, const int* in_sizes, int n_in,
                              void* d_out, int out_size)
{
    const float* x      = (const float*)d_in[0];
    const int*   mask   = (const int*)  d_in[1];
    // d_in[2] = qmask (unused by reference)
    const int*   useg   = (const int*)  d_in[3];
    const float* w_qkv  = (const float*)d_in[4];
    const float* w_fc   = (const float*)d_in[5];
    const float* b_fc   = (const float*)d_in[6];
    const float* shift  = (const float*)d_in[7];
    const float* bias_p = (const float*)d_in[8];
    float* out = (float*)d_out;

    static bool attr_set = false;
    if (!attr_set) {
        cudaFuncSetAttribute(gemm_pk_kernel,
                             cudaFuncAttributeMaxDynamicSharedMemorySize, DSMEM_BYTES);
        cudaFuncSetAttribute(attn_mma_kernel,
                             cudaFuncAttributeMaxDynamicSharedMemorySize, ASMEM);
        attr_set = true;
    }

    char *xpk, *wqpk, *wfpk, *opk;
    cudaGetSymbolAddress((void**)&xpk,  g_xpk);
    cudaGetSymbolAddress((void**)&wqpk, g_wqpk);
    cudaGetSymbolAddress((void**)&wfpk, g_wfpk);
    cudaGetSymbolAddress((void**)&opk,  g_opk);

    split_pack_b_kernel<<<2048, 256>>>(x,     xpk,  MTOT);
    split_pack_b_kernel<<<768,  256>>>(w_qkv, wqpk, NQKV);
    split_pack_b_kernel<<<256,  256>>>(w_fc,  wfpk, DMODEL);

    gemm_pk_kernel<<<dim3(NQKV / 128, MTOT / 128), 128, DSMEM_BYTES>>>(
        xpk, wqpk, MTOT, NQKV, nullptr, nullptr, 0);
    attn_mma_kernel<<<dim3(SEQ / 128, BHD), 256, ASMEM>>>(mask, useg, shift, bias_p);
    gemm_pk_kernel<<<dim3(DMODEL / 128, MTOT / 128), 128, DSMEM_BYTES>>>(
        opk, wfpk, MTOT, DMODEL, b_fc, out, 1);
}

// round 15
// speedup vs baseline: 1.1826x; 1.1826x over previous
#include <cuda_runtime.h>
#include <cuda_bf16.h>
#include <cuda_fp16.h>
#include <math.h>
#include <stdint.h>

// Problem constants (fixed by setup_inputs)
#define BATCH 4
#define SEQ   2048
#define DMODEL 1024
#define NHEAD 16
#define DHEAD 64
#define BHD   (BATCH * NHEAD)          // 64
#define MTOT  (BATCH * SEQ)            // 8192
#define NQKV  (3 * DMODEL)             // 3072

// ---------------------------------------------------------------------------
// Scratch (sanctioned: __device__ globals)
// GEMM operands fp16 hi-only: [k-chunk(32)][row][64B], 16B segs swizzled
// by (seg ^ ((row>>1)&3)). One (chunk,128-row) slice = contiguous 8 KB.
// ---------------------------------------------------------------------------
__device__ __align__(128) char g_xpk [(size_t)MTOT  * DMODEL * 2];
__device__ __align__(128) char g_wqpk[(size_t)NQKV  * DMODEL * 2];
__device__ __align__(128) char g_wfpk[(size_t)DMODEL* DMODEL * 2];
__device__ __align__(128) char g_opk [(size_t)MTOT  * DMODEL * 2];
// q/k/v for attention: fp16, [b,h,s,dh] (written by qkv GEMM epilogue)
__device__ __align__(128) __half g_q[BHD * SEQ * DHEAD];
__device__ __align__(128) __half g_k[BHD * SEQ * DHEAD];
__device__ __align__(128) __half g_v[BHD * SEQ * DHEAD];

// ---------------------------------------------------------------------------
// helpers
// ---------------------------------------------------------------------------
__device__ __forceinline__ uint32_t smem_u32(const void* p) {
    uint32_t a;
    asm("{ .reg .u64 t; cvta.to.shared.u64 t, %1; cvt.u32.u64 %0, t; }"
        : "=r"(a) : "l"(p));
    return a;
}

#define LDSM_X4(r0, r1, r2, r3, addr)                                       \
    asm volatile("ldmatrix.sync.aligned.m8n8.x4.shared.b16 {%0,%1,%2,%3}, [%4];" \
                 : "=r"(r0), "=r"(r1), "=r"(r2), "=r"(r3) : "r"(addr))

#define LDSM_X4_T(r0, r1, r2, r3, addr)                                     \
    asm volatile("ldmatrix.sync.aligned.m8n8.x4.trans.shared.b16 {%0,%1,%2,%3}, [%4];" \
                 : "=r"(r0), "=r"(r1), "=r"(r2), "=r"(r3) : "r"(addr))

__device__ __forceinline__ void mma_fp16(float* d, const uint32_t* a,
                                         uint32_t b0, uint32_t b1) {
    asm volatile(
        "mma.sync.aligned.m16n8k16.row.col.f32.f16.f16.f32 "
        "{%0,%1,%2,%3}, {%4,%5,%6,%7}, {%8,%9}, {%0,%1,%2,%3};"
        : "+f"(d[0]), "+f"(d[1]), "+f"(d[2]), "+f"(d[3])
        : "r"(a[0]), "r"(a[1]), "r"(a[2]), "r"(a[3]), "r"(b0), "r"(b1));
}

#define CP_ASYNC16(dst, src) \
    asm volatile("cp.async.cg.shared.global [%0], [%1], 16;" \
                 :: "r"(dst), "l"(src) : "memory")
#define CP_COMMIT()  asm volatile("cp.async.commit_group;" ::: "memory")
#define CP_WAIT(n)   asm volatile("cp.async.wait_group %0;" :: "n"(n) : "memory")

#define MBAR_INIT(addr, cnt) \
    asm volatile("mbarrier.init.shared.b64 [%0], %1;" :: "r"(addr), "r"((uint32_t)(cnt)) : "memory")
#define MBAR_EXPECT_TX(addr, bytes) \
    asm volatile("mbarrier.arrive.expect_tx.shared.b64 _, [%0], %1;" \
                 :: "r"(addr), "r"((uint32_t)(bytes)) : "memory")
#define MBAR_ARRIVE(addr) \
    asm volatile("mbarrier.arrive.shared.b64 _, [%0];" :: "r"(addr) : "memory")
#define BULK_G2S(dst, src, bytes, mbar) \
    asm volatile("cp.async.bulk.shared::cluster.global.mbarrier::complete_tx::bytes " \
                 "[%0], [%1], %2, [%3];" \
                 :: "r"(dst), "l"(src), "r"((uint32_t)(bytes)), "r"(mbar) : "memory")

__device__ __forceinline__ void mbar_wait(uint32_t addr, uint32_t parity) {
    asm volatile(
        "{\n\t.reg .pred P;\n\t"
        "WL%=:\n\t"
        "mbarrier.try_wait.parity.acquire.cta.shared::cta.b64 P, [%0], %1, 0x989680;\n\t"
        "@!P bra WL%=;\n\t}"
        :: "r"(addr), "r"(parity) : "memory");
}

__device__ __forceinline__ uint32_t pack2h(float a, float b) {
    __half2 h = __floats2half2_rn(a, b);
    return *(uint32_t*)&h;
}

// exp2 via magic-number rounding + deg-5 poly + exponent-bit add (no MUFU).
__device__ __forceinline__ float exp2_poly(float x) {
    x = fmaxf(x, -80.0f);
    float t = x + 12582912.0f;
    float fn = t - 12582912.0f;
    float f = x - fn;
    float p = 1.3333558e-3f;
    p = fmaf(p, f, 9.6181291e-3f);
    p = fmaf(p, f, 5.5504109e-2f);
    p = fmaf(p, f, 2.4022651e-1f);
    p = fmaf(p, f, 6.9314718e-1f);
    p = fmaf(p, f, 1.0f);
    int n = (__float_as_int(t) & 0x7FFFFF) - 0x400000;
    return __int_as_float(__float_as_int(p) + (n << 23));
}

// ---------------------------------------------------------------------------
// Pre-pass: fp32 [M,1024] -> packed swizzled fp16 hi-only chunks (64B rows)
// ---------------------------------------------------------------------------
__global__ __launch_bounds__(256) void split_pack_b_kernel(
    const float* __restrict__ src, char* __restrict__ dst, int M)
{
    const int total = M * 128;
    for (int idx = blockIdx.x * blockDim.x + threadIdx.x; idx < total;
         idx += gridDim.x * blockDim.x) {
        const int m   = idx >> 7;
        const int k   = (idx & 127) << 3;
        const int c   = k >> 5;
        const int seg = (k & 31) >> 3;   // 0..3
        const float4 v0 = *(const float4*)(src + (size_t)m * DMODEL + k);
        const float4 v1 = *(const float4*)(src + (size_t)m * DMODEL + k + 4);
        char* row = dst + ((size_t)c * M + m) * 64;
        const int sx = (m >> 1) & 3;
        *(uint4*)(row + ((seg ^ sx) << 4)) =
            make_uint4(pack2h(v0.x, v0.y), pack2h(v0.z, v0.w),
                       pack2h(v1.x, v1.y), pack2h(v1.z, v1.w));
    }
}

// ---------------------------------------------------------------------------
// fp16 1-pass GEMM (R13 config): C = Ah * Bh^T.
// 128x128 CTA tile, 4 warps (2x2 grid of 64x64 warp tiles), 128 threads,
// 2 CTA/SM. K-chunk 64 (two packed 32-sub-chunks). Stage = 32KB, 3 stages.
// ---------------------------------------------------------------------------
#define NCHK   16
#define STG_B  32768
#define DSMEM_BYTES (3 * STG_B)   // 98304

__global__ __launch_bounds__(128, 2) void gemm_pk_kernel(
    const char* __restrict__ Apk, const char* __restrict__ Bpk,
    int Mtot, int Ntot,
    const float* __restrict__ bias, float* __restrict__ out, int mode)
{
    extern __shared__ __align__(128) char dsm[];
    __shared__ __align__(8) uint64_t fullb[3];
    __shared__ __align__(8) uint64_t emptyb[3];
    const uint32_t sbase = smem_u32(dsm);
    const uint32_t fb0 = smem_u32(&fullb[0]);
    const uint32_t eb0 = smem_u32(&emptyb[0]);

    const int tid  = threadIdx.x;
    const int lane = tid & 31;
    const int warp = tid >> 5;             // 0..3
    const int bm = blockIdx.y * 128;
    const int bn = blockIdx.x * 128;
    const int warp_m = (warp >> 1) << 6;   // 0 or 64
    const int warp_n = (warp & 1) << 6;    // 0 or 64

    if (tid == 0) {
#pragma unroll
        for (int s = 0; s < 3; ++s) {
            MBAR_INIT(fb0 + s * 8, 1);
            MBAR_INIT(eb0 + s * 8, 4);
        }
    }
    __syncthreads();

    auto issue = [&](int c) {
        const int st = c % 3;
        const uint32_t mb = fb0 + st * 8;
        const uint32_t sb = sbase + st * STG_B;
        MBAR_EXPECT_TX(mb, 32768);
        BULK_G2S(sb,         Apk + ((size_t)(2*c)   * Mtot + bm) * 64, 8192, mb);
        BULK_G2S(sb + 8192,  Apk + ((size_t)(2*c+1) * Mtot + bm) * 64, 8192, mb);
        BULK_G2S(sb + 16384, Bpk + ((size_t)(2*c)   * Ntot + bn) * 64, 8192, mb);
        BULK_G2S(sb + 24576, Bpk + ((size_t)(2*c+1) * Ntot + bn) * 64, 8192, mb);
    };

    if (tid == 0) { issue(0); issue(1); }

    float acc[4][8][4];
#pragma unroll
    for (int i = 0; i < 4; i++)
#pragma unroll
        for (int j = 0; j < 8; j++)
#pragma unroll
            for (int r = 0; r < 4; r++) acc[i][j][r] = 0.f;

    const int r16 = lane & 15;
    const int cs  = lane >> 4;          // 0/1
    const int sx  = (r16 >> 1) & 3;     // 64B-row swizzle

    for (int c = 0; c < NCHK; ++c) {
        const int st = c % 3;
        mbar_wait(fb0 + st * 8, (c / 3) & 1);   // per-warp gate

#pragma unroll
        for (int kb = 0; kb < 2; ++kb) {
            const uint32_t Ast = sbase + st * STG_B + kb * 8192;
            const uint32_t Bst = Ast + 16384;
#pragma unroll
            for (int kh = 0; kh < 2; ++kh) {
                const int seg = kh * 2 + cs;        // 0..3
                uint32_t ah[4][4];
#pragma unroll
                for (int mi = 0; mi < 4; ++mi) {
                    const uint32_t ad = Ast + (warp_m + (mi << 4) + r16) * 64
                                        + ((seg ^ sx) << 4);
                    LDSM_X4(ah[mi][0], ah[mi][1], ah[mi][2], ah[mi][3], ad);
                }
#pragma unroll
                for (int g = 0; g < 4; ++g) {
                    const uint32_t bd = Bst + (warp_n + (g << 4) + r16) * 64
                                        + ((seg ^ sx) << 4);
                    uint32_t t0, t1, t2, t3;
                    LDSM_X4(t0, t1, t2, t3, bd);
#pragma unroll
                    for (int mi = 0; mi < 4; ++mi) {
                        mma_fp16(acc[mi][g * 2],     ah[mi], t0, t2);
                        mma_fp16(acc[mi][g * 2 + 1], ah[mi], t1, t3);
                    }
                }
            }
        }

        if (lane == 0) MBAR_ARRIVE(eb0 + st * 8);   // this warp done with st

        // producer: issue chunk c+2; stage (c+2)%3 was last used by chunk c-1
        if (tid == 0 && c + 2 < NCHK) {
            if (c >= 1) {
                const int s2 = (c + 2) % 3;
                mbar_wait(eb0 + s2 * 8, (((c - 1) / 3)) & 1);
            }
            issue(c + 2);
        }
    }

    // ---- epilogue ----
    const int er = lane >> 2;          // 0..7
    const int ec = (lane & 3) << 1;    // 0,2,4,6
#pragma unroll
    for (int mi = 0; mi < 4; ++mi) {
#pragma unroll
        for (int nj = 0; nj < 8; ++nj) {
            const int m = bm + warp_m + (mi << 4) + er;
            const int n = bn + warp_n + (nj << 3) + ec;
            if (mode == 0) {
                const int bb = m >> 11;
                const int ss = m & (SEQ - 1);
                const int sec = n >> 10;
                const int e = n & (DMODEL - 1);
                const int h = e >> 6;
                const int dh = e & 63;
                __half* dst = (sec == 0 ? g_q : (sec == 1 ? g_k : g_v));
                const long idx = ((long)(bb * NHEAD + h) * SEQ + ss) * DHEAD + dh;
                *(uint32_t*)(dst + idx) = pack2h(acc[mi][nj][0], acc[mi][nj][1]);
                *(uint32_t*)(dst + idx + 8 * DHEAD) =
                    pack2h(acc[mi][nj][2], acc[mi][nj][3]);
            } else {
                const float2 bv = *(const float2*)(bias + n);
                float* dst = out + (long)m * DMODEL + n;
                *(float2*)dst = make_float2(acc[mi][nj][0] + bv.x, acc[mi][nj][1] + bv.y);
                *(float2*)(dst + 8 * DMODEL) =
                    make_float2(acc[mi][nj][2] + bv.x, acc[mi][nj][3] + bv.y);
            }
        }
    }
}

// ---------------------------------------------------------------------------
// Attention via fp16 1-pass mma.sync (R13 shape: 64 queries/CTA, 128 thr),
// now with DOUBLE-BUFFERED K/V (+mask): next tile's loads overlap current
// tile's compute. Epilogue writes packed-swizzled fp16 O.
// ---------------------------------------------------------------------------
#define APITCH 144
#define ATILE  (64 * APITCH)                 // 9216
#define ASMEM  (5 * ATILE + 512)             // Q + 2x(K,V) + 2 masks

__global__ __launch_bounds__(128) void attn_mma_kernel(
    const int* __restrict__ mask, const int* __restrict__ use_g_p,
    const float* __restrict__ shift_p, const float* __restrict__ bias_pp)
{
    extern __shared__ __align__(128) char asmem[];
    const uint32_t QT  = smem_u32(asmem);
    const uint32_t KV0 = QT + ATILE;             // buf0: K | V
    // buf b: K at KV0 + b*2*ATILE, V at +ATILE
    float* msk_s = (float*)(asmem + 5 * ATILE); // [2][64]

    const int bh = blockIdx.y;
    const int bb = bh >> 4;
    const int q0 = blockIdx.x * 64;
    const int tid  = threadIdx.x;
    const int lane = tid & 31;
    const int warp = tid >> 5;

    const float LOG2E = 1.4426950408889634f;
    const float shift = shift_p[0];
    const int   useg  = use_g_p[0];
    const float sg = useg ? shift * LOG2E : 0.f;
    const float bg = useg ? bias_pp[0] * LOG2E : 0.f;
    const float SCL = 0.125f * LOG2E;

    int klo = 0, khi = SEQ;
    if (useg) {
        const int Wi = (int)sqrtf(44.f / shift) + 50;
        klo = q0 - Wi;            if (klo < 0)   klo = 0;   klo &= ~63;
        khi = (q0 + 64 + Wi + 63) & ~63;
        if (khi > SEQ) khi = SEQ;
    }

    // K/V + mask tile loader (issues cp.asyncs; no commit/wait here)
    auto issue_kv = [&](int kt, int b) {
        const uint32_t KB = KV0 + b * 2 * ATILE;
        const uint32_t VB = KB + ATILE;
#pragma unroll
        for (int it = 0; it < 4; ++it) {
            const int i = tid + (it << 7);
            const int r = i >> 3, ch = (i & 7) << 4;
            const long gb = (long)(bh * SEQ + kt + r) * DHEAD;
            CP_ASYNC16(KB + r * APITCH + ch, (const char*)(g_k + gb) + ch);
            CP_ASYNC16(VB + r * APITCH + ch, (const char*)(g_v + gb) + ch);
        }
        if (tid < 64)
            msk_s[b * 64 + tid] =
                (mask[bb * SEQ + kt + tid] != 0) ? 0.f : -1.0e5f;
    };

    // ---- prologue: Q tile + first K/V tile ----
    const long qgb = (long)(bh * SEQ + q0) * DHEAD;
    for (int i = tid; i < 512; i += 128) {
        const int r = i >> 3, ch = (i & 7) << 4;
        CP_ASYNC16(QT + r * APITCH + ch, (const char*)(g_q + qgb + r * DHEAD) + ch);
    }
    CP_COMMIT();
    issue_kv(klo, 0);
    CP_COMMIT();
    CP_WAIT(1);            // Q done
    __syncthreads();

    uint32_t aq[4][4];
    {
        const uint32_t ad0 = QT + (warp * 16 + (lane & 15)) * APITCH
                             + ((lane >> 4) << 4);
#pragma unroll
        for (int kk = 0; kk < 4; kk++)
            LDSM_X4(aq[kk][0], aq[kk][1], aq[kk][2], aq[kk][3], ad0 + kk * 32);
    }

    float o[8][4];
#pragma unroll
    for (int nb = 0; nb < 8; nb++)
#pragma unroll
        for (int r = 0; r < 4; r++) o[nb][r] = 0.f;
    float m_i[2] = {-3.0e5f, -3.0e5f};
    float l_i[2] = {0.f, 0.f};

    const int qi0 = q0 + warp * 16 + (lane >> 2);
    const int cj0 = (lane & 3) << 1;

    int buf = 0;
    for (int kt = klo; kt < khi; kt += 64) {
        // top sync: all warps finished computing the buffer we're about to
        // overwrite (buf^1, computed two tiles ago / prologue-free first iter)
        __syncthreads();
        if (kt + 64 < khi) {
            issue_kv(kt + 64, buf ^ 1);
            CP_COMMIT();
            CP_WAIT(1);    // current tile's group complete
        } else {
            CP_WAIT(0);
        }
        __syncthreads();

        const uint32_t KB = KV0 + buf * 2 * ATILE;
        const uint32_t VB = KB + ATILE;
        const float* mk = msk_s + buf * 64;

        float s[8][4];
#pragma unroll
        for (int nb = 0; nb < 8; nb++)
#pragma unroll
            for (int r = 0; r < 4; r++) s[nb][r] = 0.f;

#pragma unroll
        for (int kk = 0; kk < 4; kk++) {
#pragma unroll
            for (int g = 0; g < 4; g++) {
                const uint32_t bd = KB + (g * 16 + (lane & 15)) * APITCH
                                    + kk * 32 + ((lane >> 4) << 4);
                uint32_t t0, t1, t2, t3;
                LDSM_X4(t0, t1, t2, t3, bd);
                mma_fp16(s[g * 2],     aq[kk], t0, t2);
                mma_fp16(s[g * 2 + 1], aq[kk], t1, t3);
            }
        }

        float mx0 = -3.0e38f, mx1 = -3.0e38f;
#pragma unroll
        for (int nb = 0; nb < 8; nb++) {
            const int kj = kt + nb * 8 + cj0;
            const float mk0 = mk[nb * 8 + cj0];
            const float mk1 = mk[nb * 8 + cj0 + 1];
            const float d00 = (float)(qi0 - kj);
            const float d01 = d00 - 1.f;
            const float d20 = d00 + 8.f;
            const float d21 = d01 + 8.f;
            s[nb][0] = fmaf(s[nb][0], SCL, mk0) - fmaf(sg * d00, d00, bg);
            s[nb][1] = fmaf(s[nb][1], SCL, mk1) - fmaf(sg * d01, d01, bg);
            s[nb][2] = fmaf(s[nb][2], SCL, mk0) - fmaf(sg * d20, d20, bg);
            s[nb][3] = fmaf(s[nb][3], SCL, mk1) - fmaf(sg * d21, d21, bg);
            mx0 = fmaxf(mx0, fmaxf(s[nb][0], s[nb][1]));
            mx1 = fmaxf(mx1, fmaxf(s[nb][2], s[nb][3]));
        }
        mx0 = fmaxf(mx0, __shfl_xor_sync(0xffffffffu, mx0, 1));
        mx0 = fmaxf(mx0, __shfl_xor_sync(0xffffffffu, mx0, 2));
        mx1 = fmaxf(mx1, __shfl_xor_sync(0xffffffffu, mx1, 1));
        mx1 = fmaxf(mx1, __shfl_xor_sync(0xffffffffu, mx1, 2));
        const float mn0 = fmaxf(m_i[0], mx0);
        const float mn1 = fmaxf(m_i[1], mx1);
        const float cr0 = exp2_poly(m_i[0] - mn0);
        const float cr1 = exp2_poly(m_i[1] - mn1);
        m_i[0] = mn0; m_i[1] = mn1;

        float rs0 = 0.f, rs1 = 0.f;
#pragma unroll
        for (int nb = 0; nb < 8; nb++) {
            s[nb][0] = exp2_poly(s[nb][0] - mn0);
            s[nb][1] = exp2_poly(s[nb][1] - mn0);
            s[nb][2] = exp2_poly(s[nb][2] - mn1);
            s[nb][3] = exp2_poly(s[nb][3] - mn1);
            rs0 += s[nb][0] + s[nb][1];
            rs1 += s[nb][2] + s[nb][3];
        }
        rs0 += __shfl_xor_sync(0xffffffffu, rs0, 1);
        rs0 += __shfl_xor_sync(0xffffffffu, rs0, 2);
        rs1 += __shfl_xor_sync(0xffffffffu, rs1, 1);
        rs1 += __shfl_xor_sync(0xffffffffu, rs1, 2);
        l_i[0] = l_i[0] * cr0 + rs0;
        l_i[1] = l_i[1] * cr1 + rs1;
#pragma unroll
        for (int nb = 0; nb < 8; nb++) {
            o[nb][0] *= cr0; o[nb][1] *= cr0;
            o[nb][2] *= cr1; o[nb][3] *= cr1;
        }

#pragma unroll
        for (int kk = 0; kk < 4; kk++) {
            uint32_t ph[4];
            ph[0] = pack2h(s[2 * kk][0],     s[2 * kk][1]);
            ph[1] = pack2h(s[2 * kk][2],     s[2 * kk][3]);
            ph[2] = pack2h(s[2 * kk + 1][0], s[2 * kk + 1][1]);
            ph[3] = pack2h(s[2 * kk + 1][2], s[2 * kk + 1][3]);
#pragma unroll
            for (int gn = 0; gn < 4; gn++) {
                const uint32_t vd = VB + (kk * 16 + (lane & 15)) * APITCH
                                    + gn * 32 + ((lane >> 4) << 4);
                uint32_t t0, t1, t2, t3;
                LDSM_X4_T(t0, t1, t2, t3, vd);
                mma_fp16(o[gn * 2],     ph, t0, t1);
                mma_fp16(o[gn * 2 + 1], ph, t2, t3);
            }
        }
        buf ^= 1;
    }

    // ---- normalize + write O in packed-swizzled fp16 hi-only layout ----
    const float inv0 = 1.f / l_i[0];
    const float inv1 = 1.f / l_i[1];
    const int h = bh & 15;
    const int mrow = bb * SEQ + q0 + warp * 16 + (lane >> 2);
    const int swx = (mrow >> 1) & 3;
#pragma unroll
    for (int nb = 0; nb < 8; nb++) {
        const int d0 = nb * 8 + cj0;
        const int c  = 2 * h + (d0 >> 5);
        const int kk = d0 & 31;
        const int off = (((kk >> 3) ^ swx) << 4) + ((kk & 7) << 1);
        char* r1 = g_opk + ((size_t)c * MTOT + mrow) * 64;
        char* r2 = r1 + 8 * 64;
        *(uint32_t*)(r1 + off) = pack2h(o[nb][0] * inv0, o[nb][1] * inv0);
        *(uint32_t*)(r2 + off) = pack2h(o[nb][2] * inv1, o[nb][3] * inv1);
    }
}

// ---------------------------------------------------------------------------
extern "C" void kernel_launch(void* const* d_in, const int* in_sizes, int n_in,
                              void* d_out, int out_size)
{
    const float* x      = (const float*)d_in[0];
    const int*   mask   = (const int*)  d_in[1];
    // d_in[2] = qmask (unused by reference)
    const int*   useg   = (const int*)  d_in[3];
    const float* w_qkv  = (const float*)d_in[4];
    const float* w_fc   = (const float*)d_in[5];
    const float* b_fc   = (const float*)d_in[6];
    const float* shift  = (const float*)d_in[7];
    const float* bias_p = (const float*)d_in[8];
    float* out = (float*)d_out;

    static bool attr_set = false;
    if (!attr_set) {
        cudaFuncSetAttribute(gemm_pk_kernel,
                             cudaFuncAttributeMaxDynamicSharedMemorySize, DSMEM_BYTES);
        cudaFuncSetAttribute(attn_mma_kernel,
                             cudaFuncAttributeMaxDynamicSharedMemorySize, ASMEM);
        attr_set = true;
    }

    char *xpk, *wqpk, *wfpk, *opk;
    cudaGetSymbolAddress((void**)&xpk,  g_xpk);
    cudaGetSymbolAddress((void**)&wqpk, g_wqpk);
    cudaGetSymbolAddress((void**)&wfpk, g_wfpk);
    cudaGetSymbolAddress((void**)&opk,  g_opk);

    split_pack_b_kernel<<<2048, 256>>>(x,     xpk,  MTOT);
    split_pack_b_kernel<<<768,  256>>>(w_qkv, wqpk, NQKV);
    split_pack_b_kernel<<<256,  256>>>(w_fc,  wfpk, DMODEL);

    gemm_pk_kernel<<<dim3(NQKV / 128, MTOT / 128), 128, DSMEM_BYTES>>>(
        xpk, wqpk, MTOT, NQKV, nullptr, nullptr, 0);
    attn_mma_kernel<<<dim3(SEQ / 64, BHD), 128, ASMEM>>>(mask, useg, shift, bias_p);
    gemm_pk_kernel<<<dim3(DMODEL / 128, MTOT / 128), 128, DSMEM_BYTES>>>(
        opk, wfpk, MTOT, DMODEL, b_fc, out, 1);
}